// round 1
// baseline (speedup 1.0000x reference)
#include <cuda_runtime.h>
#include <math.h>

#define BATCH 16384
#define B6 (BATCH*6)
#define H 128
#define DTc 0.01f
#define WARPS 12
#define TPB (WARPS*32)
#define NBLK 152

// ---- shared-memory weight layout (float offsets) ----
#define OFF_S1L 0        // [12][128]  W1L^T
#define OFF_S2L 1536     // [128][128] W2L^T
#define OFF_S3L 17920    // [128][21]  W3L^T
#define OFF_B1L 20608
#define OFF_B2L 20736
#define OFF_B3L 20864    // 24 slots (21 used)
#define OFF_S1V 20888    // [12][128]  W1V^T
#define OFF_S2V 22424    // [128][128] W2V^T(in-major)
#define OFF_W3V 38808    // [128]
#define OFF_B1V 38936
#define OFF_B2V 39064
#define WTOT    39192
#define SCR     1280     // per-warp scratch floats
#define SMEM_FLOATS (WTOT + WARPS*SCR)
#define SMEM_BYTES  (SMEM_FLOATS*4)

// per-warp scratch sublayout (float offsets within scr)
// vecs  [896]  @0     : 7 x 128 (h + 6 tangents), reused by V-net buffers
// ydy   [147]  @896   : y (21) + 6 x dy (21)
// dmj   [126]  @1048
// psm   [21]   @1176
// gsm   [6]    @1200
// rhssm [6]    @1208
// qsh   [6]    @1216
// qdsh  [6]    @1224
// tcsm  [6]    @1232
// tssm  [6]    @1240

__device__ float g_qs[B6];
__device__ float g_qds[B6];
__device__ float g_kqd[4][B6];
__device__ unsigned g_mask[4];

__constant__ float c_LOWER[6]  = {-6.28f,-6.28f,-3.14f,-6.28f,-6.28f,-6.28f};
__constant__ float c_UPPER[6]  = { 6.28f, 6.28f, 3.14f, 6.28f, 6.28f, 6.28f};
__constant__ float c_EFFORT[6] = {150.f,150.f,150.f,28.f,28.f,28.f};
__constant__ int   c_TI[21] = {0,1,1,2,2,2,3,3,3,3,4,4,4,4,4,5,5,5,5,5,5};
__constant__ int   c_TJ[21] = {0,0,1,0,1,2,0,1,2,3,0,1,2,3,4,0,1,2,3,4,5};

__device__ __forceinline__ float sp_f(float x){
    // jax.nn.softplus = logaddexp(x, 0) = max(x,0) + log1p(exp(-|x|))
    return fmaxf(x, 0.0f) + log1pf(expf(-fabsf(x)));
}
__device__ __forceinline__ float sig_f(float x){
    return 1.0f / (1.0f + expf(-x));
}
__device__ __forceinline__ float wsum(float v){
    #pragma unroll
    for (int o = 16; o; o >>= 1) v += __shfl_xor_sync(0xffffffffu, v, o);
    return v;
}

// ---------------- mask zeroing ----------------
__global__ void zeroMaskK(){
    if (threadIdx.x < 4) g_mask[threadIdx.x] = 0u;
}

// ---------------- stage state + violation mask ----------------
__global__ void stageAK(const float* __restrict__ obs, int stage){
    int e = blockIdx.x*blockDim.x + threadIdx.x;
    unsigned bits = 0u;
    if (e < BATCH){
        #pragma unroll
        for (int i = 0; i < 6; i++){
            float q  = obs[e*12 + i];
            float qd = obs[e*12 + 6 + i];
            float qs, qds;
            if (stage == 0){
                qs = q; qds = qd;
            } else if (stage == 1){
                float k1 = g_kqd[0][e*6+i];
                float k1q = qd;
                qs  = q + 0.5f*DTc*k1q;
                qds = qd + 0.5f*DTc*k1;
            } else if (stage == 2){
                float k1 = g_kqd[0][e*6+i];
                float k2 = g_kqd[1][e*6+i];
                float k2q = qd + 0.5f*DTc*k1;
                qs  = q + 0.5f*DTc*k2q;
                qds = qd + 0.5f*DTc*k2;
            } else {
                float k2 = g_kqd[1][e*6+i];
                float k3 = g_kqd[2][e*6+i];
                float k3q = qd + 0.5f*DTc*k2;
                qs  = q + DTc*k3q;
                qds = qd + DTc*k3;
            }
            g_qs[e*6+i]  = qs;
            g_qds[e*6+i] = qds;
            float lo = c_LOWER[i] + 0.1f;
            float up = c_UPPER[i] - 0.1f;
            if (qs <= lo || qs >= up) bits |= (1u << i);
        }
    }
    if (bits) atomicOr(&g_mask[stage], bits);
}

// ---------------- heavy accel kernel ----------------
__global__ void __launch_bounds__(TPB, 1) stageBK(
    const float* __restrict__ W1L, const float* __restrict__ b1L,
    const float* __restrict__ W2L, const float* __restrict__ b2L,
    const float* __restrict__ W3L, const float* __restrict__ b3L,
    const float* __restrict__ W1V, const float* __restrict__ b1V,
    const float* __restrict__ W2V, const float* __restrict__ b2V,
    const float* __restrict__ W3V, const float* __restrict__ action,
    int stage)
{
    extern __shared__ float s[];
    const int tid = threadIdx.x;

    // stage weights (transposed to in-major) into shared
    for (int i = tid; i < 12*H; i += TPB) s[OFF_S1L + (i%12)*H + i/12] = W1L[i];
    for (int i = tid; i < H*H;  i += TPB) s[OFF_S2L + (i%H)*H + i/H]  = W2L[i];
    for (int i = tid; i < 21*H; i += TPB) s[OFF_S3L + (i%H)*21 + i/H] = W3L[i];
    for (int i = tid; i < 12*H; i += TPB) s[OFF_S1V + (i%12)*H + i/12] = W1V[i];
    for (int i = tid; i < H*H;  i += TPB) s[OFF_S2V + (i%H)*H + i/H]  = W2V[i];
    for (int i = tid; i < H; i += TPB){
        s[OFF_B1L+i]=b1L[i]; s[OFF_B2L+i]=b2L[i];
        s[OFF_B1V+i]=b1V[i]; s[OFF_B2V+i]=b2V[i];
        s[OFF_W3V+i]=W3V[i];
    }
    for (int i = tid; i < 21; i += TPB) s[OFF_B3L+i]=b3L[i];
    __syncthreads();

    const unsigned mask = g_mask[stage];
    const int wid = tid >> 5, lane = tid & 31;
    float* scr   = s + WTOT + wid*SCR;
    float* vecs  = scr;
    float* ydy   = scr + 896;
    float* dmj   = scr + 1048;
    float* psm   = scr + 1176;
    float* gsm   = scr + 1200;
    float* rhssm = scr + 1208;
    float* qsh   = scr + 1216;
    float* qdsh  = scr + 1224;
    float* tcsm  = scr + 1232;
    float* tssm  = scr + 1240;
    const int o0 = lane*4;
    float* kout = g_kqd[stage];

    for (int e = blockIdx.x*WARPS + wid; e < BATCH; e += gridDim.x*WARPS){
        if (lane < 6){
            float qv  = g_qs[e*6+lane];
            float qdv = g_qds[e*6+lane];
            qsh[lane]  = qv;
            qdsh[lane] = qdv;
            float sn, cs;
            sincosf(qv, &sn, &cs);
            tcsm[lane] = cs;
            tssm[lane] = sn;
        }
        __syncwarp();
        float tc[6], tsn[6], qdr[6];
        #pragma unroll
        for (int i = 0; i < 6; i++){ tc[i]=tcsm[i]; tsn[i]=tssm[i]; qdr[i]=qdsh[i]; }

        // ---- L net layer 1: h1 + 6 tangents
        {
            float zz[4];
            #pragma unroll
            for (int m=0;m<4;m++) zz[m] = s[OFF_B1L+o0+m];
            #pragma unroll
            for (int k=0;k<12;k++){
                float tk = (k&1) ? tsn[k>>1] : tc[k>>1];
                float4 w = *(const float4*)&s[OFF_S1L + k*H + o0];
                zz[0]+=w.x*tk; zz[1]+=w.y*tk; zz[2]+=w.z*tk; zz[3]+=w.w*tk;
            }
            float s1[4];
            #pragma unroll
            for (int m=0;m<4;m++){
                vecs[o0+m] = sp_f(zz[m]);
                s1[m] = sig_f(zz[m]);
            }
            #pragma unroll
            for (int j=0;j<6;j++){
                float4 wa = *(const float4*)&s[OFF_S1L + (2*j  )*H + o0];
                float4 wb = *(const float4*)&s[OFF_S1L + (2*j+1)*H + o0];
                float cj = tc[j], sj = tsn[j];
                vecs[(j+1)*H + o0 + 0] = s1[0]*(wb.x*cj - wa.x*sj);
                vecs[(j+1)*H + o0 + 1] = s1[1]*(wb.y*cj - wa.y*sj);
                vecs[(j+1)*H + o0 + 2] = s1[2]*(wb.z*cj - wa.z*sj);
                vecs[(j+1)*H + o0 + 3] = s1[3]*(wb.w*cj - wa.w*sj);
            }
        }
        __syncwarp();

        // ---- L net layer 2, fused over 7 vectors
        float acc[7][4];
        #pragma unroll
        for (int m=0;m<4;m++) acc[0][m] = s[OFF_B2L+o0+m];
        #pragma unroll
        for (int v=1;v<7;v++){
            #pragma unroll
            for (int m=0;m<4;m++) acc[v][m]=0.f;
        }
        for (int k=0;k<H;k+=4){
            float hv[7][4];
            #pragma unroll
            for (int v=0;v<7;v++){
                float4 h4 = *(const float4*)&vecs[v*H + k];
                hv[v][0]=h4.x; hv[v][1]=h4.y; hv[v][2]=h4.z; hv[v][3]=h4.w;
            }
            #pragma unroll
            for (int kk=0;kk<4;kk++){
                float4 w = *(const float4*)&s[OFF_S2L + (k+kk)*H + o0];
                #pragma unroll
                for (int v=0;v<7;v++){
                    acc[v][0] += w.x*hv[v][kk];
                    acc[v][1] += w.y*hv[v][kk];
                    acc[v][2] += w.z*hv[v][kk];
                    acc[v][3] += w.w*hv[v][kk];
                }
            }
        }
        __syncwarp();
        {
            float s2[4];
            #pragma unroll
            for (int m=0;m<4;m++) s2[m] = sig_f(acc[0][m]);
            #pragma unroll
            for (int m=0;m<4;m++) vecs[o0+m] = sp_f(acc[0][m]);
            #pragma unroll
            for (int v=1;v<7;v++){
                #pragma unroll
                for (int m=0;m<4;m++) vecs[v*H+o0+m] = s2[m]*acc[v][m];
            }
        }
        __syncwarp();

        // ---- L net layer 3 (21 outputs) -> y, dy_j
        if (lane < 21){
            float f7[7];
            f7[0] = s[OFF_B3L+lane];
            #pragma unroll
            for (int v=1;v<7;v++) f7[v]=0.f;
            for (int k=0;k<H;k+=4){
                float w0 = s[OFF_S3L+(k+0)*21+lane];
                float w1 = s[OFF_S3L+(k+1)*21+lane];
                float w2 = s[OFF_S3L+(k+2)*21+lane];
                float w3 = s[OFF_S3L+(k+3)*21+lane];
                #pragma unroll
                for (int v=0;v<7;v++){
                    float4 h4 = *(const float4*)&vecs[v*H + k];
                    f7[v] += w0*h4.x + w1*h4.y + w2*h4.z + w3*h4.w;
                }
            }
            float s3 = sig_f(f7[0]);
            ydy[lane] = sp_f(f7[0]);
            #pragma unroll
            for (int v=1;v<7;v++) ydy[v*21+lane] = s3*f7[v];
        }
        __syncwarp();

        // ---- V net layer 1: hv1, sv1
        {
            float zz[4];
            #pragma unroll
            for (int m=0;m<4;m++) zz[m] = s[OFF_B1V+o0+m];
            #pragma unroll
            for (int k=0;k<12;k++){
                float tk = (k&1) ? tsn[k>>1] : tc[k>>1];
                float4 w = *(const float4*)&s[OFF_S1V + k*H + o0];
                zz[0]+=w.x*tk; zz[1]+=w.y*tk; zz[2]+=w.z*tk; zz[3]+=w.w*tk;
            }
            #pragma unroll
            for (int m=0;m<4;m++){
                vecs[o0+m]   = sp_f(zz[m]);   // hv1
                vecs[H+o0+m] = sig_f(zz[m]);  // sv1
            }
        }
        __syncwarp();

        // ---- V net layer 2 forward -> a2 = W3V .* sigmoid(z2v)
        {
            float a4[4];
            #pragma unroll
            for (int m=0;m<4;m++) a4[m] = s[OFF_B2V+o0+m];
            for (int k=0;k<H;k+=4){
                float4 h4 = *(const float4*)&vecs[k];
                float hh[4] = {h4.x, h4.y, h4.z, h4.w};
                #pragma unroll
                for (int kk=0;kk<4;kk++){
                    float4 w = *(const float4*)&s[OFF_S2V + (k+kk)*H + o0];
                    a4[0]+=w.x*hh[kk]; a4[1]+=w.y*hh[kk];
                    a4[2]+=w.z*hh[kk]; a4[3]+=w.w*hh[kk];
                }
            }
            __syncwarp();
            #pragma unroll
            for (int m=0;m<4;m++) vecs[2*H+o0+m] = s[OFF_W3V+o0+m]*sig_f(a4[m]);
        }
        __syncwarp();

        // ---- gbar1 = W2V^T a2 ; a1 = gbar1 .* sv1
        {
            float a2r[4];
            #pragma unroll
            for (int m2=0;m2<4;m2++) a2r[m2] = vecs[2*H + lane + 32*m2];
            for (int k=0;k<H;k++){
                float p = s[OFF_S2V + k*H + lane     ]*a2r[0]
                        + s[OFF_S2V + k*H + lane + 32]*a2r[1]
                        + s[OFF_S2V + k*H + lane + 64]*a2r[2]
                        + s[OFF_S2V + k*H + lane + 96]*a2r[3];
                p = wsum(p);
                if (lane == 0) vecs[3*H+k] = p*vecs[H+k];
            }
        }
        __syncwarp();

        // ---- gt = W1V^T a1 ; g_j = cos*gt[2j+1] - sin*gt[2j]
        {
            float a1r[4];
            #pragma unroll
            for (int m2=0;m2<4;m2++) a1r[m2] = vecs[3*H + lane + 32*m2];
            #pragma unroll
            for (int k=0;k<12;k++){
                float p = s[OFF_S1V + k*H + lane     ]*a1r[0]
                        + s[OFF_S1V + k*H + lane + 32]*a1r[1]
                        + s[OFF_S1V + k*H + lane + 64]*a1r[2]
                        + s[OFF_S1V + k*H + lane + 96]*a1r[3];
                p = wsum(p);
                if (lane == 0) vecs[4*H+k] = p;
            }
            __syncwarp();
            if (lane < 6)
                gsm[lane] = tcsm[lane]*vecs[4*H+2*lane+1] - tssm[lane]*vecs[4*H+2*lane];
        }
        __syncwarp();

        // ---- dM_j lower-tri entries: (dM_j)_ab = sum_m dL[a,m]L[b,m] + L[a,m]dL[b,m]
        for (int t = lane; t < 126; t += 32){
            int j = t/21, u = t%21;
            int a = c_TI[u], b = c_TJ[u];
            int ta = a*(a+1)/2, tb = b*(b+1)/2;
            const float* Lr = ydy;
            const float* Dr = ydy + (j+1)*21;
            float sacc = 0.f;
            for (int m = 0; m <= b; m++)
                sacc += Dr[ta+m]*Lr[tb+m] + Lr[ta+m]*Dr[tb+m];
            dmj[t] = sacc;
        }
        __syncwarp();

        // ---- P = sum_j qdot_j dM_j
        if (lane < 21){
            float p = 0.f;
            #pragma unroll
            for (int j=0;j<6;j++) p += qdr[j]*dmj[j*21+lane];
            psm[lane] = p;
        }
        __syncwarp();

        // ---- c_i, constraints, rhs
        if (lane < 6){
            int i = lane;
            float c1 = 0.f;
            #pragma unroll
            for (int b=0;b<6;b++){
                int idx = (i >= b) ? (i*(i+1)/2 + b) : (b*(b+1)/2 + i);
                c1 += psm[idx]*qdr[b];
            }
            float qf = 0.f;   // 0.5 * qd^T dM_i qd
            for (int u2=0; u2<21; u2++){
                int a = c_TI[u2], b = c_TJ[u2];
                float w = (a==b) ? 0.5f : 1.0f;
                qf += w*dmj[i*21+u2]*qdsh[a]*qdsh[b];
            }
            float ci = c1 - qf;
            float qi = qsh[i];
            float lo = c_LOWER[i] + 0.1f;
            float up = c_UPPER[i] - 0.1f;
            float fi;
            if (mask & (1u << i))
                fi = (qi <= lo) ? c_EFFORT[i] : ((qi >= up) ? -c_EFFORT[i] : 0.0f);
            else
                fi = -5.0f*(1.0f/(qi-lo) - 1.0f/(up-qi));
            float tau = action[e*6+i]*c_EFFORT[i];
            rhssm[i] = tau - ci - gsm[i] - fi;
        }
        __syncwarp();

        // ---- solve (L L^T) x = rhs via fwd/back substitution
        if (lane == 0){
            float Lm[6][6];
            #pragma unroll
            for (int i=0;i<6;i++){
                #pragma unroll
                for (int jj=0;jj<6;jj++)
                    Lm[i][jj] = (jj<=i) ? ydy[i*(i+1)/2+jj] : 0.f;
            }
            float wv[6], x[6];
            #pragma unroll
            for (int i=0;i<6;i++){
                float sr = rhssm[i];
                #pragma unroll
                for (int jj=0;jj<6;jj++) if (jj < i) sr -= Lm[i][jj]*wv[jj];
                wv[i] = sr / Lm[i][i];
            }
            #pragma unroll
            for (int i=5;i>=0;i--){
                float sr = wv[i];
                #pragma unroll
                for (int jj=0;jj<6;jj++) if (jj > i) sr -= Lm[jj][i]*x[jj];
                x[i] = sr / Lm[i][i];
            }
            #pragma unroll
            for (int i=0;i<6;i++) kout[e*6+i] = x[i];
        }
        __syncwarp();
    }
}

// ---------------- final RK4 combine ----------------
__global__ void stageFK(const float* __restrict__ obs, float* __restrict__ out){
    int e = blockIdx.x*blockDim.x + threadIdx.x;
    if (e >= BATCH) return;
    #pragma unroll
    for (int i=0;i<6;i++){
        float q  = obs[e*12 + i];
        float qd = obs[e*12 + 6 + i];
        float k1 = g_kqd[0][e*6+i];
        float k2 = g_kqd[1][e*6+i];
        float k3 = g_kqd[2][e*6+i];
        float k4 = g_kqd[3][e*6+i];
        float k1q = qd;
        float k2q = qd + 0.5f*DTc*k1;
        float k3q = qd + 0.5f*DTc*k2;
        float k4q = qd + DTc*k3;
        float qn  = q  + (DTc/6.0f)*(k1q + 2.f*k2q + 2.f*k3q + k4q);
        float qdn = qd + (DTc/6.0f)*(k1  + 2.f*k2  + 2.f*k3  + k4 );
        qn = fminf(fmaxf(qn, c_LOWER[i]), c_UPPER[i]);
        out[e*12 + i]     = qn;
        out[e*12 + 6 + i] = qdn;
    }
}

extern "C" void kernel_launch(void* const* d_in, const int* in_sizes, int n_in,
                              void* d_out, int out_size)
{
    const float* obs    = (const float*)d_in[0];
    const float* action = (const float*)d_in[1];
    const float* W1L = (const float*)d_in[2];  const float* b1L = (const float*)d_in[3];
    const float* W2L = (const float*)d_in[4];  const float* b2L = (const float*)d_in[5];
    const float* W3L = (const float*)d_in[6];  const float* b3L = (const float*)d_in[7];
    const float* W1V = (const float*)d_in[8];  const float* b1V = (const float*)d_in[9];
    const float* W2V = (const float*)d_in[10]; const float* b2V = (const float*)d_in[11];
    const float* W3V = (const float*)d_in[12];
    float* out = (float*)d_out;

    cudaFuncSetAttribute(stageBK, cudaFuncAttributeMaxDynamicSharedMemorySize, SMEM_BYTES);

    zeroMaskK<<<1, 32>>>();
    for (int st = 0; st < 4; st++){
        stageAK<<<BATCH/256, 256>>>(obs, st);
        stageBK<<<NBLK, TPB, SMEM_BYTES>>>(W1L,b1L,W2L,b2L,W3L,b3L,
                                           W1V,b1V,W2V,b2V,W3V, action, st);
    }
    stageFK<<<BATCH/256, 256>>>(obs, out);
}

// round 2
// speedup vs baseline: 1.2105x; 1.2105x over previous
#include <cuda_runtime.h>
#include <math.h>

#define BATCH 16384
#define B6 (BATCH*6)
#define H 128
#define DTc 0.01f
#define WARPS 13
#define TPB (WARPS*32)
#define NBLK 152

// ---- shared-memory weight layout (float offsets) ----
#define OFF_S1L 0        // [12][128]  W1L^T
#define OFF_S2L 1536     // [128][128] W2L^T (in-major)
#define OFF_S3L 17920    // [128][21]  W3L^T
#define OFF_B1L 20608
#define OFF_B2L 20736
#define OFF_B3L 20864    // 24 slots (21 used)
#define OFF_S1V 20888    // [12][128]  W1V^T
#define OFF_S2V 22424    // [128][128] W2V^T (in-major)
#define OFF_W3V 38808    // [128]
#define OFF_B1V 38936
#define OFF_B2V 39064
#define WTOT    39192
#define SCR     1280     // per-warp scratch floats
#define SMEM_FLOATS (WTOT + WARPS*SCR)
#define SMEM_BYTES  (SMEM_FLOATS*4)

__device__ float g_qs[B6];
__device__ float g_qds[B6];
__device__ float g_kqd[4][B6];
__device__ unsigned g_mask[4];

__constant__ float c_LOWER[6]  = {-6.28f,-6.28f,-3.14f,-6.28f,-6.28f,-6.28f};
__constant__ float c_UPPER[6]  = { 6.28f, 6.28f, 3.14f, 6.28f, 6.28f, 6.28f};
__constant__ float c_EFFORT[6] = {150.f,150.f,150.f,28.f,28.f,28.f};
__constant__ int   c_TI[21] = {0,1,1,2,2,2,3,3,3,3,4,4,4,4,4,5,5,5,5,5,5};
__constant__ int   c_TJ[21] = {0,0,1,0,1,2,0,1,2,3,0,1,2,3,4,0,1,2,3,4,5};

// fast softplus + sigmoid sharing one exp
__device__ __forceinline__ void spsig(float x, float& sp, float& sg){
    float e = __expf(-fabsf(x));
    float r = __fdividef(1.0f, 1.0f + e);
    sp = fmaxf(x, 0.0f) + __logf(1.0f + e);
    sg = (x >= 0.0f) ? r : (1.0f - r);
}
__device__ __forceinline__ float sig_f(float x){
    float e = __expf(-fabsf(x));
    float r = __fdividef(1.0f, 1.0f + e);
    return (x >= 0.0f) ? r : (1.0f - r);
}
__device__ __forceinline__ float wsum(float v){
    #pragma unroll
    for (int o = 16; o; o >>= 1) v += __shfl_xor_sync(0xffffffffu, v, o);
    return v;
}

// ---------------- mask zeroing ----------------
__global__ void zeroMaskK(){
    if (threadIdx.x < 4) g_mask[threadIdx.x] = 0u;
}

// ---------------- stage state + violation mask ----------------
__global__ void stageAK(const float* __restrict__ obs, int stage){
    int e = blockIdx.x*blockDim.x + threadIdx.x;
    unsigned bits = 0u;
    if (e < BATCH){
        #pragma unroll
        for (int i = 0; i < 6; i++){
            float q  = obs[e*12 + i];
            float qd = obs[e*12 + 6 + i];
            float qs, qds;
            if (stage == 0){
                qs = q; qds = qd;
            } else if (stage == 1){
                float k1 = g_kqd[0][e*6+i];
                qs  = q + 0.5f*DTc*qd;
                qds = qd + 0.5f*DTc*k1;
            } else if (stage == 2){
                float k1 = g_kqd[0][e*6+i];
                float k2 = g_kqd[1][e*6+i];
                float k2q = qd + 0.5f*DTc*k1;
                qs  = q + 0.5f*DTc*k2q;
                qds = qd + 0.5f*DTc*k2;
            } else {
                float k2 = g_kqd[1][e*6+i];
                float k3 = g_kqd[2][e*6+i];
                float k3q = qd + 0.5f*DTc*k2;
                qs  = q + DTc*k3q;
                qds = qd + DTc*k3;
            }
            g_qs[e*6+i]  = qs;
            g_qds[e*6+i] = qds;
            float lo = c_LOWER[i] + 0.1f;
            float up = c_UPPER[i] - 0.1f;
            if (qs <= lo || qs >= up) bits |= (1u << i);
        }
    }
    if (bits) atomicOr(&g_mask[stage], bits);
}

// ---------------- heavy accel kernel ----------------
__global__ void __launch_bounds__(TPB, 1) stageBK(
    const float* __restrict__ W1L, const float* __restrict__ b1L,
    const float* __restrict__ W2L, const float* __restrict__ b2L,
    const float* __restrict__ W3L, const float* __restrict__ b3L,
    const float* __restrict__ W1V, const float* __restrict__ b1V,
    const float* __restrict__ W2V, const float* __restrict__ b2V,
    const float* __restrict__ W3V, const float* __restrict__ action,
    int stage)
{
    extern __shared__ float s[];
    const int tid = threadIdx.x;

    // stage weights (transposed to in-major) into shared
    for (int i = tid; i < 12*H; i += TPB) s[OFF_S1L + (i%12)*H + i/12] = W1L[i];
    for (int i = tid; i < H*H;  i += TPB) s[OFF_S2L + (i%H)*H + i/H]  = W2L[i];
    for (int i = tid; i < 21*H; i += TPB) s[OFF_S3L + (i%H)*21 + i/H] = W3L[i];
    for (int i = tid; i < 12*H; i += TPB) s[OFF_S1V + (i%12)*H + i/12] = W1V[i];
    for (int i = tid; i < H*H;  i += TPB) s[OFF_S2V + (i%H)*H + i/H]  = W2V[i];
    for (int i = tid; i < H; i += TPB){
        s[OFF_B1L+i]=b1L[i]; s[OFF_B2L+i]=b2L[i];
        s[OFF_B1V+i]=b1V[i]; s[OFF_B2V+i]=b2V[i];
        s[OFF_W3V+i]=W3V[i];
    }
    for (int i = tid; i < 21; i += TPB) s[OFF_B3L+i]=b3L[i];
    __syncthreads();

    const unsigned mask = g_mask[stage];
    const int wid = tid >> 5, lane = tid & 31;
    float* scr   = s + WTOT + wid*SCR;
    float* vecs  = scr;
    float* ydy   = scr + 896;
    float* dmj   = scr + 1048;
    float* psm   = scr + 1176;
    float* gsm   = scr + 1200;
    float* rhssm = scr + 1208;
    float* qsh   = scr + 1216;
    float* qdsh  = scr + 1224;
    float* tcsm  = scr + 1232;
    float* tssm  = scr + 1240;
    const int o0 = lane*4;
    float* kout = g_kqd[stage];

    for (int e = blockIdx.x*WARPS + wid; e < BATCH; e += gridDim.x*WARPS){
        if (lane < 6){
            float qv  = g_qs[e*6+lane];
            float qdv = g_qds[e*6+lane];
            qsh[lane]  = qv;
            qdsh[lane] = qdv;
            float sn, cs;
            __sincosf(qv, &sn, &cs);
            tcsm[lane] = cs;
            tssm[lane] = sn;
        }
        __syncwarp();
        float tc[6], tsn[6], qdr[6];
        #pragma unroll
        for (int i = 0; i < 6; i++){ tc[i]=tcsm[i]; tsn[i]=tssm[i]; qdr[i]=qdsh[i]; }

        // ==================== L network ====================
        // ---- layer 1: h1 + 6 tangents
        {
            float zz[4];
            #pragma unroll
            for (int m=0;m<4;m++) zz[m] = s[OFF_B1L+o0+m];
            #pragma unroll
            for (int k=0;k<12;k++){
                float tk = (k&1) ? tsn[k>>1] : tc[k>>1];
                float4 w = *(const float4*)&s[OFF_S1L + k*H + o0];
                zz[0]+=w.x*tk; zz[1]+=w.y*tk; zz[2]+=w.z*tk; zz[3]+=w.w*tk;
            }
            float s1[4];
            #pragma unroll
            for (int m=0;m<4;m++){
                float spv, sgv; spsig(zz[m], spv, sgv);
                vecs[o0+m] = spv; s1[m] = sgv;
            }
            #pragma unroll
            for (int j=0;j<6;j++){
                float4 wa = *(const float4*)&s[OFF_S1L + (2*j  )*H + o0];
                float4 wb = *(const float4*)&s[OFF_S1L + (2*j+1)*H + o0];
                float cj = tc[j], sj = tsn[j];
                vecs[(j+1)*H + o0 + 0] = s1[0]*(wb.x*cj - wa.x*sj);
                vecs[(j+1)*H + o0 + 1] = s1[1]*(wb.y*cj - wa.y*sj);
                vecs[(j+1)*H + o0 + 2] = s1[2]*(wb.z*cj - wa.z*sj);
                vecs[(j+1)*H + o0 + 3] = s1[3]*(wb.w*cj - wa.w*sj);
            }
        }
        __syncwarp();

        // ---- layer 2, fused over 7 vectors
        {
            float acc[7][4];
            #pragma unroll
            for (int m=0;m<4;m++) acc[0][m] = s[OFF_B2L+o0+m];
            #pragma unroll
            for (int v=1;v<7;v++){
                #pragma unroll
                for (int m=0;m<4;m++) acc[v][m]=0.f;
            }
            for (int k=0;k<H;k+=4){
                float hv[7][4];
                #pragma unroll
                for (int v=0;v<7;v++){
                    float4 h4 = *(const float4*)&vecs[v*H + k];
                    hv[v][0]=h4.x; hv[v][1]=h4.y; hv[v][2]=h4.z; hv[v][3]=h4.w;
                }
                #pragma unroll
                for (int kk=0;kk<4;kk++){
                    float4 w = *(const float4*)&s[OFF_S2L + (k+kk)*H + o0];
                    #pragma unroll
                    for (int v=0;v<7;v++){
                        acc[v][0] += w.x*hv[v][kk];
                        acc[v][1] += w.y*hv[v][kk];
                        acc[v][2] += w.z*hv[v][kk];
                        acc[v][3] += w.w*hv[v][kk];
                    }
                }
            }
            __syncwarp();
            float s2[4];
            #pragma unroll
            for (int m=0;m<4;m++){
                float spv, sgv; spsig(acc[0][m], spv, sgv);
                vecs[o0+m] = spv; s2[m] = sgv;
            }
            #pragma unroll
            for (int v=1;v<7;v++){
                #pragma unroll
                for (int m=0;m<4;m++) vecs[v*H+o0+m] = s2[m]*acc[v][m];
            }
        }
        __syncwarp();

        // ---- layer 3 (21 outputs) -> y, dy_j
        if (lane < 21){
            float f7[7];
            f7[0] = s[OFF_B3L+lane];
            #pragma unroll
            for (int v=1;v<7;v++) f7[v]=0.f;
            for (int k=0;k<H;k+=4){
                float w0 = s[OFF_S3L+(k+0)*21+lane];
                float w1 = s[OFF_S3L+(k+1)*21+lane];
                float w2 = s[OFF_S3L+(k+2)*21+lane];
                float w3 = s[OFF_S3L+(k+3)*21+lane];
                #pragma unroll
                for (int v=0;v<7;v++){
                    float4 h4 = *(const float4*)&vecs[v*H + k];
                    f7[v] += w0*h4.x + w1*h4.y + w2*h4.z + w3*h4.w;
                }
            }
            float spv, s3; spsig(f7[0], spv, s3);
            ydy[lane] = spv;
            #pragma unroll
            for (int v=1;v<7;v++) ydy[v*21+lane] = s3*f7[v];
        }
        __syncwarp();

        // ==================== V network (forward-mode gradient) ====================
        // ---- layer 1: value + 6 tangents (overwrite vecs)
        {
            float zz[4];
            #pragma unroll
            for (int m=0;m<4;m++) zz[m] = s[OFF_B1V+o0+m];
            #pragma unroll
            for (int k=0;k<12;k++){
                float tk = (k&1) ? tsn[k>>1] : tc[k>>1];
                float4 w = *(const float4*)&s[OFF_S1V + k*H + o0];
                zz[0]+=w.x*tk; zz[1]+=w.y*tk; zz[2]+=w.z*tk; zz[3]+=w.w*tk;
            }
            float s1[4];
            #pragma unroll
            for (int m=0;m<4;m++){
                float spv, sgv; spsig(zz[m], spv, sgv);
                vecs[o0+m] = spv; s1[m] = sgv;
            }
            #pragma unroll
            for (int j=0;j<6;j++){
                float4 wa = *(const float4*)&s[OFF_S1V + (2*j  )*H + o0];
                float4 wb = *(const float4*)&s[OFF_S1V + (2*j+1)*H + o0];
                float cj = tc[j], sj = tsn[j];
                vecs[(j+1)*H + o0 + 0] = s1[0]*(wb.x*cj - wa.x*sj);
                vecs[(j+1)*H + o0 + 1] = s1[1]*(wb.y*cj - wa.y*sj);
                vecs[(j+1)*H + o0 + 2] = s1[2]*(wb.z*cj - wa.z*sj);
                vecs[(j+1)*H + o0 + 3] = s1[3]*(wb.w*cj - wa.w*sj);
            }
        }
        __syncwarp();

        // ---- layer 2 fused over 7 vectors + gravity dot with W3V
        {
            float acc[7][4];
            #pragma unroll
            for (int m=0;m<4;m++) acc[0][m] = s[OFF_B2V+o0+m];
            #pragma unroll
            for (int v=1;v<7;v++){
                #pragma unroll
                for (int m=0;m<4;m++) acc[v][m]=0.f;
            }
            for (int k=0;k<H;k+=4){
                float hv[7][4];
                #pragma unroll
                for (int v=0;v<7;v++){
                    float4 h4 = *(const float4*)&vecs[v*H + k];
                    hv[v][0]=h4.x; hv[v][1]=h4.y; hv[v][2]=h4.z; hv[v][3]=h4.w;
                }
                #pragma unroll
                for (int kk=0;kk<4;kk++){
                    float4 w = *(const float4*)&s[OFF_S2V + (k+kk)*H + o0];
                    #pragma unroll
                    for (int v=0;v<7;v++){
                        acc[v][0] += w.x*hv[v][kk];
                        acc[v][1] += w.y*hv[v][kk];
                        acc[v][2] += w.z*hv[v][kk];
                        acc[v][3] += w.w*hv[v][kk];
                    }
                }
            }
            float pj[6];
            #pragma unroll
            for (int j=0;j<6;j++) pj[j]=0.f;
            #pragma unroll
            for (int m=0;m<4;m++){
                float wv = s[OFF_W3V+o0+m] * sig_f(acc[0][m]);
                #pragma unroll
                for (int j=0;j<6;j++) pj[j] += wv*acc[j+1][m];
            }
            #pragma unroll
            for (int j=0;j<6;j++){
                float g = wsum(pj[j]);
                if (lane == 0) gsm[j] = g;
            }
        }
        __syncwarp();

        // ---- dM_j lower-tri entries
        for (int t = lane; t < 126; t += 32){
            int j = t/21, u = t%21;
            int a = c_TI[u], b = c_TJ[u];
            int ta = a*(a+1)/2, tb = b*(b+1)/2;
            const float* Lr = ydy;
            const float* Dr = ydy + (j+1)*21;
            float sacc = 0.f;
            for (int m = 0; m <= b; m++)
                sacc += Dr[ta+m]*Lr[tb+m] + Lr[ta+m]*Dr[tb+m];
            dmj[t] = sacc;
        }
        __syncwarp();

        // ---- P = sum_j qdot_j dM_j
        if (lane < 21){
            float p = 0.f;
            #pragma unroll
            for (int j=0;j<6;j++) p += qdr[j]*dmj[j*21+lane];
            psm[lane] = p;
        }
        __syncwarp();

        // ---- c_i, constraints, rhs
        if (lane < 6){
            int i = lane;
            float c1 = 0.f;
            #pragma unroll
            for (int b=0;b<6;b++){
                int idx = (i >= b) ? (i*(i+1)/2 + b) : (b*(b+1)/2 + i);
                c1 += psm[idx]*qdr[b];
            }
            float qf = 0.f;   // 0.5 * qd^T dM_i qd
            for (int u2=0; u2<21; u2++){
                int a = c_TI[u2], b = c_TJ[u2];
                float w = (a==b) ? 0.5f : 1.0f;
                qf += w*dmj[i*21+u2]*qdsh[a]*qdsh[b];
            }
            float ci = c1 - qf;
            float qi = qsh[i];
            float lo = c_LOWER[i] + 0.1f;
            float up = c_UPPER[i] - 0.1f;
            float fi;
            if (mask & (1u << i))
                fi = (qi <= lo) ? c_EFFORT[i] : ((qi >= up) ? -c_EFFORT[i] : 0.0f);
            else
                fi = -5.0f*(__fdividef(1.0f, qi-lo) - __fdividef(1.0f, up-qi));
            float tau = action[e*6+i]*c_EFFORT[i];
            rhssm[i] = tau - ci - gsm[i] - fi;
        }
        __syncwarp();

        // ---- solve (L L^T) x = rhs via fwd/back substitution
        if (lane == 0){
            float Lm[6][6];
            #pragma unroll
            for (int i=0;i<6;i++){
                #pragma unroll
                for (int jj=0;jj<6;jj++)
                    Lm[i][jj] = (jj<=i) ? ydy[i*(i+1)/2+jj] : 0.f;
            }
            float rinv[6];
            #pragma unroll
            for (int i=0;i<6;i++) rinv[i] = __fdividef(1.0f, Lm[i][i]);
            float wv[6], x[6];
            #pragma unroll
            for (int i=0;i<6;i++){
                float sr = rhssm[i];
                #pragma unroll
                for (int jj=0;jj<6;jj++) if (jj < i) sr -= Lm[i][jj]*wv[jj];
                wv[i] = sr * rinv[i];
            }
            #pragma unroll
            for (int i=5;i>=0;i--){
                float sr = wv[i];
                #pragma unroll
                for (int jj=0;jj<6;jj++) if (jj > i) sr -= Lm[jj][i]*x[jj];
                x[i] = sr * rinv[i];
            }
            #pragma unroll
            for (int i=0;i<6;i++) kout[e*6+i] = x[i];
        }
        __syncwarp();
    }
}

// ---------------- final RK4 combine ----------------
__global__ void stageFK(const float* __restrict__ obs, float* __restrict__ out){
    int e = blockIdx.x*blockDim.x + threadIdx.x;
    if (e >= BATCH) return;
    #pragma unroll
    for (int i=0;i<6;i++){
        float q  = obs[e*12 + i];
        float qd = obs[e*12 + 6 + i];
        float k1 = g_kqd[0][e*6+i];
        float k2 = g_kqd[1][e*6+i];
        float k3 = g_kqd[2][e*6+i];
        float k4 = g_kqd[3][e*6+i];
        float k1q = qd;
        float k2q = qd + 0.5f*DTc*k1;
        float k3q = qd + 0.5f*DTc*k2;
        float k4q = qd + DTc*k3;
        float qn  = q  + (DTc/6.0f)*(k1q + 2.f*k2q + 2.f*k3q + k4q);
        float qdn = qd + (DTc/6.0f)*(k1  + 2.f*k2  + 2.f*k3  + k4 );
        qn = fminf(fmaxf(qn, c_LOWER[i]), c_UPPER[i]);
        out[e*12 + i]     = qn;
        out[e*12 + 6 + i] = qdn;
    }
}

extern "C" void kernel_launch(void* const* d_in, const int* in_sizes, int n_in,
                              void* d_out, int out_size)
{
    const float* obs    = (const float*)d_in[0];
    const float* action = (const float*)d_in[1];
    const float* W1L = (const float*)d_in[2];  const float* b1L = (const float*)d_in[3];
    const float* W2L = (const float*)d_in[4];  const float* b2L = (const float*)d_in[5];
    const float* W3L = (const float*)d_in[6];  const float* b3L = (const float*)d_in[7];
    const float* W1V = (const float*)d_in[8];  const float* b1V = (const float*)d_in[9];
    const float* W2V = (const float*)d_in[10]; const float* b2V = (const float*)d_in[11];
    const float* W3V = (const float*)d_in[12];
    float* out = (float*)d_out;

    cudaFuncSetAttribute(stageBK, cudaFuncAttributeMaxDynamicSharedMemorySize, SMEM_BYTES);

    zeroMaskK<<<1, 32>>>();
    for (int st = 0; st < 4; st++){
        stageAK<<<BATCH/256, 256>>>(obs, st);
        stageBK<<<NBLK, TPB, SMEM_BYTES>>>(W1L,b1L,W2L,b2L,W3L,b3L,
                                           W1V,b1V,W2V,b2V,W3V, action, st);
    }
    stageFK<<<BATCH/256, 256>>>(obs, out);
}

// round 4
// speedup vs baseline: 1.2805x; 1.0578x over previous
#include <cuda_runtime.h>
#include <math.h>

#define BATCH 16384
#define B6 (BATCH*6)
#define H 128
#define DTc 0.01f
#define WARPS 13
#define TPB (WARPS*32)
#define NBLK 152

// ---- shared-memory weight layout (float offsets) ----
#define OFF_S1L 0        // [12][128]  W1L^T
#define OFF_S2L 1536     // [128][128] W2L^T (in-major)
#define OFF_S3L 17920    // [128][21]  W3L^T
#define OFF_B1L 20608
#define OFF_B2L 20736
#define OFF_B3L 20864    // 24 slots (21 used)
#define OFF_S1V 20888    // [12][128]  W1V^T
#define OFF_S2V 22424    // [128][128] W2V^T (in-major)
#define OFF_W3V 38808    // [128]
#define OFF_B1V 38936
#define OFF_B2V 39064
#define WTOT    39192
#define SCR     1280     // per-warp scratch floats
#define SMEM_FLOATS (WTOT + WARPS*SCR)
#define SMEM_BYTES  (SMEM_FLOATS*4)

typedef unsigned long long ull;

__device__ float g_qs[B6];
__device__ float g_qds[B6];
__device__ float g_kqd[4][B6];
__device__ unsigned g_mask[4];

__constant__ float c_LOWER[6]  = {-6.28f,-6.28f,-3.14f,-6.28f,-6.28f,-6.28f};
__constant__ float c_UPPER[6]  = { 6.28f, 6.28f, 3.14f, 6.28f, 6.28f, 6.28f};
__constant__ float c_EFFORT[6] = {150.f,150.f,150.f,28.f,28.f,28.f};
__constant__ int   c_TI[21] = {0,1,1,2,2,2,3,3,3,3,4,4,4,4,4,5,5,5,5,5,5};
__constant__ int   c_TJ[21] = {0,0,1,0,1,2,0,1,2,3,0,1,2,3,4,0,1,2,3,4,5};

// ---- packed fp32x2 helpers (Blackwell FFMA2 path) ----
__device__ __forceinline__ ull pk2(float a, float b){
    ull r; asm("mov.b64 %0, {%1, %2};" : "=l"(r) : "f"(a), "f"(b)); return r;
}
__device__ __forceinline__ void upk2(ull v, float& a, float& b){
    asm("mov.b64 {%0, %1}, %2;" : "=f"(a), "=f"(b) : "l"(v));
}
__device__ __forceinline__ ull ffma2(ull a, ull b, ull c){
    ull d; asm("fma.rn.f32x2 %0, %1, %2, %3;" : "=l"(d) : "l"(a), "l"(b), "l"(c)); return d;
}

// fast softplus + sigmoid sharing one exp
__device__ __forceinline__ void spsig(float x, float& sp, float& sg){
    float e = __expf(-fabsf(x));
    float r = __fdividef(1.0f, 1.0f + e);
    sp = fmaxf(x, 0.0f) + __logf(1.0f + e);
    sg = (x >= 0.0f) ? r : (1.0f - r);
}
__device__ __forceinline__ float sig_f(float x){
    float e = __expf(-fabsf(x));
    float r = __fdividef(1.0f, 1.0f + e);
    return (x >= 0.0f) ? r : (1.0f - r);
}
__device__ __forceinline__ float wsum(float v){
    #pragma unroll
    for (int o = 16; o; o >>= 1) v += __shfl_xor_sync(0xffffffffu, v, o);
    return v;
}

// ---------------- mask zeroing ----------------
__global__ void zeroMaskK(){
    if (threadIdx.x < 4) g_mask[threadIdx.x] = 0u;
}

// ---------------- stage state + violation mask ----------------
__global__ void stageAK(const float* __restrict__ obs, int stage){
    int e = blockIdx.x*blockDim.x + threadIdx.x;
    unsigned bits = 0u;
    if (e < BATCH){
        #pragma unroll
        for (int i = 0; i < 6; i++){
            float q  = obs[e*12 + i];
            float qd = obs[e*12 + 6 + i];
            float qs, qds;
            if (stage == 0){
                qs = q; qds = qd;
            } else if (stage == 1){
                float k1 = g_kqd[0][e*6+i];
                qs  = q + 0.5f*DTc*qd;
                qds = qd + 0.5f*DTc*k1;
            } else if (stage == 2){
                float k1 = g_kqd[0][e*6+i];
                float k2 = g_kqd[1][e*6+i];
                float k2q = qd + 0.5f*DTc*k1;
                qs  = q + 0.5f*DTc*k2q;
                qds = qd + 0.5f*DTc*k2;
            } else {
                float k2 = g_kqd[1][e*6+i];
                float k3 = g_kqd[2][e*6+i];
                float k3q = qd + 0.5f*DTc*k2;
                qs  = q + DTc*k3q;
                qds = qd + DTc*k3;
            }
            g_qs[e*6+i]  = qs;
            g_qds[e*6+i] = qds;
            float lo = c_LOWER[i] + 0.1f;
            float up = c_UPPER[i] - 0.1f;
            if (qs <= lo || qs >= up) bits |= (1u << i);
        }
    }
    if (bits) atomicOr(&g_mask[stage], bits);
}

// ---------------- heavy accel kernel ----------------
__global__ void __launch_bounds__(TPB, 1) stageBK(
    const float* __restrict__ W1L, const float* __restrict__ b1L,
    const float* __restrict__ W2L, const float* __restrict__ b2L,
    const float* __restrict__ W3L, const float* __restrict__ b3L,
    const float* __restrict__ W1V, const float* __restrict__ b1V,
    const float* __restrict__ W2V, const float* __restrict__ b2V,
    const float* __restrict__ W3V, const float* __restrict__ action,
    int stage)
{
    extern __shared__ float s[];
    const int tid = threadIdx.x;

    // stage weights (transposed to in-major) into shared
    for (int i = tid; i < 12*H; i += TPB) s[OFF_S1L + (i%12)*H + i/12] = W1L[i];
    for (int i = tid; i < H*H;  i += TPB) s[OFF_S2L + (i%H)*H + i/H]  = W2L[i];
    for (int i = tid; i < 21*H; i += TPB) s[OFF_S3L + (i%H)*21 + i/H] = W3L[i];
    for (int i = tid; i < 12*H; i += TPB) s[OFF_S1V + (i%12)*H + i/12] = W1V[i];
    for (int i = tid; i < H*H;  i += TPB) s[OFF_S2V + (i%H)*H + i/H]  = W2V[i];
    for (int i = tid; i < H; i += TPB){
        s[OFF_B1L+i]=b1L[i]; s[OFF_B2L+i]=b2L[i];
        s[OFF_B1V+i]=b1V[i]; s[OFF_B2V+i]=b2V[i];
        s[OFF_W3V+i]=W3V[i];
    }
    for (int i = tid; i < 21; i += TPB) s[OFF_B3L+i]=b3L[i];
    __syncthreads();

    const unsigned mask = g_mask[stage];
    const int wid = tid >> 5, lane = tid & 31;
    float* scr   = s + WTOT + wid*SCR;
    float* vecs  = scr;
    float* ydy   = scr + 896;
    float* dmj   = scr + 1048;
    float* psm   = scr + 1176;
    float* gsm   = scr + 1200;
    float* rhssm = scr + 1208;
    float* qsh   = scr + 1216;
    float* qdsh  = scr + 1224;
    float* tcsm  = scr + 1232;
    float* tssm  = scr + 1240;
    const int o0 = lane*4;
    float* kout = g_kqd[stage];

    for (int e = blockIdx.x*WARPS + wid; e < BATCH; e += gridDim.x*WARPS){
        if (lane < 6){
            float qv  = g_qs[e*6+lane];
            float qdv = g_qds[e*6+lane];
            qsh[lane]  = qv;
            qdsh[lane] = qdv;
            float sn, cs;
            __sincosf(qv, &sn, &cs);
            tcsm[lane] = cs;
            tssm[lane] = sn;
        }
        __syncwarp();
        float tc[6], tsn[6], qdr[6];
        #pragma unroll
        for (int i = 0; i < 6; i++){ tc[i]=tcsm[i]; tsn[i]=tssm[i]; qdr[i]=qdsh[i]; }

        // ==================== L network ====================
        // ---- layer 1: h1 + 6 tangents
        {
            float zz[4];
            #pragma unroll
            for (int m=0;m<4;m++) zz[m] = s[OFF_B1L+o0+m];
            #pragma unroll
            for (int k=0;k<12;k++){
                float tk = (k&1) ? tsn[k>>1] : tc[k>>1];
                float4 w = *(const float4*)&s[OFF_S1L + k*H + o0];
                zz[0]+=w.x*tk; zz[1]+=w.y*tk; zz[2]+=w.z*tk; zz[3]+=w.w*tk;
            }
            float s1[4];
            #pragma unroll
            for (int m=0;m<4;m++){
                float spv, sgv; spsig(zz[m], spv, sgv);
                vecs[o0+m] = spv; s1[m] = sgv;
            }
            #pragma unroll
            for (int j=0;j<6;j++){
                float4 wa = *(const float4*)&s[OFF_S1L + (2*j  )*H + o0];
                float4 wb = *(const float4*)&s[OFF_S1L + (2*j+1)*H + o0];
                float cj = tc[j], sj = tsn[j];
                vecs[(j+1)*H + o0 + 0] = s1[0]*(wb.x*cj - wa.x*sj);
                vecs[(j+1)*H + o0 + 1] = s1[1]*(wb.y*cj - wa.y*sj);
                vecs[(j+1)*H + o0 + 2] = s1[2]*(wb.z*cj - wa.z*sj);
                vecs[(j+1)*H + o0 + 3] = s1[3]*(wb.w*cj - wa.w*sj);
            }
        }
        __syncwarp();

        // ---- layer 2, fused over 7 vectors (packed fp32x2 over m-pairs)
        {
            ull a01[7], a23[7];
            a01[0] = pk2(s[OFF_B2L+o0+0], s[OFF_B2L+o0+1]);
            a23[0] = pk2(s[OFF_B2L+o0+2], s[OFF_B2L+o0+3]);
            #pragma unroll
            for (int v=1;v<7;v++){ a01[v]=0ull; a23[v]=0ull; }
            for (int k=0;k<H;k+=4){
                float4 h4[7];
                #pragma unroll
                for (int v=0;v<7;v++) h4[v] = *(const float4*)&vecs[v*H + k];
                #pragma unroll
                for (int kk=0;kk<4;kk++){
                    float4 w = *(const float4*)&s[OFF_S2L + (k+kk)*H + o0];
                    ull w01 = pk2(w.x, w.y), w23 = pk2(w.z, w.w);
                    #pragma unroll
                    for (int v=0;v<7;v++){
                        float hs = (&h4[v].x)[kk];
                        ull h2 = pk2(hs, hs);
                        a01[v] = ffma2(w01, h2, a01[v]);
                        a23[v] = ffma2(w23, h2, a23[v]);
                    }
                }
            }
            __syncwarp();
            float av[7][4];
            #pragma unroll
            for (int v=0;v<7;v++){
                upk2(a01[v], av[v][0], av[v][1]);
                upk2(a23[v], av[v][2], av[v][3]);
            }
            float s2[4];
            #pragma unroll
            for (int m=0;m<4;m++){
                float spv, sgv; spsig(av[0][m], spv, sgv);
                vecs[o0+m] = spv; s2[m] = sgv;
            }
            #pragma unroll
            for (int v=1;v<7;v++){
                #pragma unroll
                for (int m=0;m<4;m++) vecs[v*H+o0+m] = s2[m]*av[v][m];
            }
        }
        __syncwarp();

        // ---- layer 3 (21 outputs) -> y, dy_j
        if (lane < 21){
            float f7[7];
            f7[0] = s[OFF_B3L+lane];
            #pragma unroll
            for (int v=1;v<7;v++) f7[v]=0.f;
            for (int k=0;k<H;k+=4){
                float w0 = s[OFF_S3L+(k+0)*21+lane];
                float w1 = s[OFF_S3L+(k+1)*21+lane];
                float w2 = s[OFF_S3L+(k+2)*21+lane];
                float w3 = s[OFF_S3L+(k+3)*21+lane];
                #pragma unroll
                for (int v=0;v<7;v++){
                    float4 h4 = *(const float4*)&vecs[v*H + k];
                    f7[v] += w0*h4.x + w1*h4.y + w2*h4.z + w3*h4.w;
                }
            }
            float spv, s3; spsig(f7[0], spv, s3);
            ydy[lane] = spv;
            #pragma unroll
            for (int v=1;v<7;v++) ydy[v*21+lane] = s3*f7[v];
        }
        __syncwarp();

        // ==================== V network (forward-mode gradient) ====================
        // ---- layer 1: value + 6 tangents (overwrite vecs)
        {
            float zz[4];
            #pragma unroll
            for (int m=0;m<4;m++) zz[m] = s[OFF_B1V+o0+m];
            #pragma unroll
            for (int k=0;k<12;k++){
                float tk = (k&1) ? tsn[k>>1] : tc[k>>1];
                float4 w = *(const float4*)&s[OFF_S1V + k*H + o0];
                zz[0]+=w.x*tk; zz[1]+=w.y*tk; zz[2]+=w.z*tk; zz[3]+=w.w*tk;
            }
            float s1[4];
            #pragma unroll
            for (int m=0;m<4;m++){
                float spv, sgv; spsig(zz[m], spv, sgv);
                vecs[o0+m] = spv; s1[m] = sgv;
            }
            #pragma unroll
            for (int j=0;j<6;j++){
                float4 wa = *(const float4*)&s[OFF_S1V + (2*j  )*H + o0];
                float4 wb = *(const float4*)&s[OFF_S1V + (2*j+1)*H + o0];
                float cj = tc[j], sj = tsn[j];
                vecs[(j+1)*H + o0 + 0] = s1[0]*(wb.x*cj - wa.x*sj);
                vecs[(j+1)*H + o0 + 1] = s1[1]*(wb.y*cj - wa.y*sj);
                vecs[(j+1)*H + o0 + 2] = s1[2]*(wb.z*cj - wa.z*sj);
                vecs[(j+1)*H + o0 + 3] = s1[3]*(wb.w*cj - wa.w*sj);
            }
        }
        __syncwarp();

        // ---- layer 2 fused over 7 vectors (packed) + gravity dot with W3V
        {
            ull a01[7], a23[7];
            a01[0] = pk2(s[OFF_B2V+o0+0], s[OFF_B2V+o0+1]);
            a23[0] = pk2(s[OFF_B2V+o0+2], s[OFF_B2V+o0+3]);
            #pragma unroll
            for (int v=1;v<7;v++){ a01[v]=0ull; a23[v]=0ull; }
            for (int k=0;k<H;k+=4){
                float4 h4[7];
                #pragma unroll
                for (int v=0;v<7;v++) h4[v] = *(const float4*)&vecs[v*H + k];
                #pragma unroll
                for (int kk=0;kk<4;kk++){
                    float4 w = *(const float4*)&s[OFF_S2V + (k+kk)*H + o0];
                    ull w01 = pk2(w.x, w.y), w23 = pk2(w.z, w.w);
                    #pragma unroll
                    for (int v=0;v<7;v++){
                        float hs = (&h4[v].x)[kk];
                        ull h2 = pk2(hs, hs);
                        a01[v] = ffma2(w01, h2, a01[v]);
                        a23[v] = ffma2(w23, h2, a23[v]);
                    }
                }
            }
            float av[7][4];
            #pragma unroll
            for (int v=0;v<7;v++){
                upk2(a01[v], av[v][0], av[v][1]);
                upk2(a23[v], av[v][2], av[v][3]);
            }
            float pj[6];
            #pragma unroll
            for (int j=0;j<6;j++) pj[j]=0.f;
            #pragma unroll
            for (int m=0;m<4;m++){
                float wv = s[OFF_W3V+o0+m] * sig_f(av[0][m]);
                #pragma unroll
                for (int j=0;j<6;j++) pj[j] += wv*av[j+1][m];
            }
            #pragma unroll
            for (int j=0;j<6;j++){
                float g = wsum(pj[j]);
                if (lane == 0) gsm[j] = g;
            }
        }
        __syncwarp();

        // ---- dM_j lower-tri entries
        for (int t = lane; t < 126; t += 32){
            int j = t/21, u = t%21;
            int a = c_TI[u], b = c_TJ[u];
            int ta = a*(a+1)/2, tb = b*(b+1)/2;
            const float* Lr = ydy;
            const float* Dr = ydy + (j+1)*21;
            float sacc = 0.f;
            for (int m = 0; m <= b; m++)
                sacc += Dr[ta+m]*Lr[tb+m] + Lr[ta+m]*Dr[tb+m];
            dmj[t] = sacc;
        }
        __syncwarp();

        // ---- P = sum_j qdot_j dM_j
        if (lane < 21){
            float p = 0.f;
            #pragma unroll
            for (int j=0;j<6;j++) p += qdr[j]*dmj[j*21+lane];
            psm[lane] = p;
        }
        __syncwarp();

        // ---- c_i, constraints, rhs
        if (lane < 6){
            int i = lane;
            float c1 = 0.f;
            #pragma unroll
            for (int b=0;b<6;b++){
                int idx = (i >= b) ? (i*(i+1)/2 + b) : (b*(b+1)/2 + i);
                c1 += psm[idx]*qdr[b];
            }
            float qf = 0.f;   // 0.5 * qd^T dM_i qd
            for (int u2=0; u2<21; u2++){
                int a = c_TI[u2], b = c_TJ[u2];
                float w = (a==b) ? 0.5f : 1.0f;
                qf += w*dmj[i*21+u2]*qdsh[a]*qdsh[b];
            }
            float ci = c1 - qf;
            float qi = qsh[i];
            float lo = c_LOWER[i] + 0.1f;
            float up = c_UPPER[i] - 0.1f;
            float fi;
            if (mask & (1u << i))
                fi = (qi <= lo) ? c_EFFORT[i] : ((qi >= up) ? -c_EFFORT[i] : 0.0f);
            else
                fi = -5.0f*(__fdividef(1.0f, qi-lo) - __fdividef(1.0f, up-qi));
            float tau = action[e*6+i]*c_EFFORT[i];
            rhssm[i] = tau - ci - gsm[i] - fi;
        }
        __syncwarp();

        // ---- solve (L L^T) x = rhs via fwd/back substitution
        if (lane == 0){
            float Lm[6][6];
            #pragma unroll
            for (int i=0;i<6;i++){
                #pragma unroll
                for (int jj=0;jj<6;jj++)
                    Lm[i][jj] = (jj<=i) ? ydy[i*(i+1)/2+jj] : 0.f;
            }
            float rinv[6];
            #pragma unroll
            for (int i=0;i<6;i++) rinv[i] = __fdividef(1.0f, Lm[i][i]);
            float wv[6], x[6];
            #pragma unroll
            for (int i=0;i<6;i++){
                float sr = rhssm[i];
                #pragma unroll
                for (int jj=0;jj<6;jj++) if (jj < i) sr -= Lm[i][jj]*wv[jj];
                wv[i] = sr * rinv[i];
            }
            #pragma unroll
            for (int i=5;i>=0;i--){
                float sr = wv[i];
                #pragma unroll
                for (int jj=0;jj<6;jj++) if (jj > i) sr -= Lm[jj][i]*x[jj];
                x[i] = sr * rinv[i];
            }
            #pragma unroll
            for (int i=0;i<6;i++) kout[e*6+i] = x[i];
        }
        __syncwarp();
    }
}

// ---------------- final RK4 combine ----------------
__global__ void stageFK(const float* __restrict__ obs, float* __restrict__ out){
    int e = blockIdx.x*blockDim.x + threadIdx.x;
    if (e >= BATCH) return;
    #pragma unroll
    for (int i=0;i<6;i++){
        float q  = obs[e*12 + i];
        float qd = obs[e*12 + 6 + i];
        float k1 = g_kqd[0][e*6+i];
        float k2 = g_kqd[1][e*6+i];
        float k3 = g_kqd[2][e*6+i];
        float k4 = g_kqd[3][e*6+i];
        float k1q = qd;
        float k2q = qd + 0.5f*DTc*k1;
        float k3q = qd + 0.5f*DTc*k2;
        float k4q = qd + DTc*k3;
        float qn  = q  + (DTc/6.0f)*(k1q + 2.f*k2q + 2.f*k3q + k4q);
        float qdn = qd + (DTc/6.0f)*(k1  + 2.f*k2  + 2.f*k3  + k4 );
        qn = fminf(fmaxf(qn, c_LOWER[i]), c_UPPER[i]);
        out[e*12 + i]     = qn;
        out[e*12 + 6 + i] = qdn;
    }
}

extern "C" void kernel_launch(void* const* d_in, const int* in_sizes, int n_in,
                              void* d_out, int out_size)
{
    const float* obs    = (const float*)d_in[0];
    const float* action = (const float*)d_in[1];
    const float* W1L = (const float*)d_in[2];  const float* b1L = (const float*)d_in[3];
    const float* W2L = (const float*)d_in[4];  const float* b2L = (const float*)d_in[5];
    const float* W3L = (const float*)d_in[6];  const float* b3L = (const float*)d_in[7];
    const float* W1V = (const float*)d_in[8];  const float* b1V = (const float*)d_in[9];
    const float* W2V = (const float*)d_in[10]; const float* b2V = (const float*)d_in[11];
    const float* W3V = (const float*)d_in[12];
    float* out = (float*)d_out;

    cudaFuncSetAttribute(stageBK, cudaFuncAttributeMaxDynamicSharedMemorySize, SMEM_BYTES);

    zeroMaskK<<<1, 32>>>();
    for (int st = 0; st < 4; st++){
        stageAK<<<BATCH/256, 256>>>(obs, st);
        stageBK<<<NBLK, TPB, SMEM_BYTES>>>(W1L,b1L,W2L,b2L,W3L,b3L,
                                           W1V,b1V,W2V,b2V,W3V, action, st);
    }
    stageFK<<<BATCH/256, 256>>>(obs, out);
}